// round 3
// baseline (speedup 1.0000x reference)
#include <cuda_runtime.h>

// Problem shape (fixed by the dataset)
#define B_ROWS   16384
#define D_DIM    2048
#define D4       (D_DIM / 4)          // 512 float4 per row
#define TOTAL4   (B_ROWS * D4)        // 8,388,608 float4 total
#define NBLK     2048
#define NTHR     256

__device__ float g_partials[NBLK];

// Kernel 1: grid-stride float4 stream over inputs, accumulate
// sum over b of || x_b - standar_score[polarity[b]] ||^2 as per-block partials.
// HBM-bound: 128 MiB of x, everything else cache-resident.
__global__ __launch_bounds__(NTHR) void partial_sq_kernel(
    const float* __restrict__ x,
    const int* __restrict__ pol,      // int32 (JAX x64 disabled downcasts int64)
    const float* __restrict__ s)
{
    const float4* __restrict__ x4 = (const float4*)x;
    const float4* __restrict__ s4 = (const float4*)s;

    float acc = 0.0f;
    for (int i = blockIdx.x * NTHR + threadIdx.x; i < TOTAL4; i += NBLK * NTHR) {
        int row  = i >> 9;        // i / D4
        int c    = i & (D4 - 1);  // i % D4
        int p = __ldg(&pol[row]);
        p = min(max(p, 0), 2);    // defensive clamp: keep gather in-bounds
        float4 xv = x4[i];
        float4 sv = __ldg(&s4[p * D4 + c]);
        float d0 = xv.x - sv.x;
        float d1 = xv.y - sv.y;
        float d2 = xv.z - sv.z;
        float d3 = xv.w - sv.w;
        acc += d0 * d0 + d1 * d1 + d2 * d2 + d3 * d3;
    }

    __shared__ float sm[NTHR];
    sm[threadIdx.x] = acc;
    __syncthreads();
#pragma unroll
    for (int st = NTHR / 2; st > 0; st >>= 1) {
        if (threadIdx.x < st) sm[threadIdx.x] += sm[threadIdx.x + st];
        __syncthreads();
    }
    if (threadIdx.x == 0) g_partials[blockIdx.x] = sm[0];
}

// Kernel 2: reduce the 2048 partials and add the three cos^2 terms.
// cos_(a,b) = dot(a,b) / sqrt(||a||^2) * sqrt(||b||^2)  (reference precedence)
// => cos_^2 = dot^2 * ||b||^2 / ||a||^2
__global__ __launch_bounds__(NTHR) void final_kernel(
    const float* __restrict__ s,
    float* __restrict__ out)
{
    int tid = threadIdx.x;

    float acc = 0.0f;
    for (int i = tid; i < NBLK; i += NTHR) acc += g_partials[i];

    float n0 = 0.f, n1 = 0.f, n2 = 0.f, d01 = 0.f, d02 = 0.f, d12 = 0.f;
    for (int j = tid; j < D_DIM; j += NTHR) {
        float a = s[j];
        float b = s[D_DIM + j];
        float c = s[2 * D_DIM + j];
        n0  += a * a;  n1  += b * b;  n2  += c * c;
        d01 += a * b;  d02 += a * c;  d12 += b * c;
    }

    __shared__ float sm[7][NTHR];
    sm[0][tid] = acc;
    sm[1][tid] = n0;  sm[2][tid] = n1;  sm[3][tid] = n2;
    sm[4][tid] = d01; sm[5][tid] = d02; sm[6][tid] = d12;
    __syncthreads();
#pragma unroll
    for (int st = NTHR / 2; st > 0; st >>= 1) {
        if (tid < st) {
#pragma unroll
            for (int k = 0; k < 7; k++) sm[k][tid] += sm[k][tid + st];
        }
        __syncthreads();
    }

    if (tid == 0) {
        float L   = sm[0][0];
        float N0  = sm[1][0], N1 = sm[2][0], N2 = sm[3][0];
        float D01 = sm[4][0], D02 = sm[5][0], D12 = sm[6][0];
        float c01 = D01 * D01 * (N1 / N0);
        float c02 = D02 * D02 * (N2 / N0);
        float c12 = D12 * D12 * (N2 / N1);
        out[0] = L + c01 + c02 + c12;
    }
}

extern "C" void kernel_launch(void* const* d_in, const int* in_sizes, int n_in,
                              void* d_out, int out_size)
{
    const float* x   = (const float*)d_in[0];   // inputs [16384, 2048] f32
    const int*   pol = (const int*)d_in[1];     // polarity [16384] int32
    const float* s   = (const float*)d_in[2];   // standar_score [3, 2048] f32
    float* out = (float*)d_out;

    partial_sq_kernel<<<NBLK, NTHR>>>(x, pol, s);
    final_kernel<<<1, NTHR>>>(s, out);
}

// round 4
// speedup vs baseline: 1.0558x; 1.0558x over previous
#include <cuda_runtime.h>

// Problem shape (fixed by the dataset)
#define B_ROWS   16384
#define D_DIM    2048
#define D4       (D_DIM / 4)          // 512 float4 per row
#define TOTAL4   (B_ROWS * D4)        // 8,388,608 float4 total
#define NBLK     2048
#define NTHR     256
#define PER_THR  (TOTAL4 / (NBLK * NTHR))   // exactly 16

__device__ float g_partials[NBLK];
__device__ unsigned int g_count;   // zero-initialized at module load; reset by last block

// Single fused kernel:
//  phase 1 (all blocks): stream 128 MiB of x, per-block partial of
//      sum_b || x_b - standar_score[polarity[b]] ||^2
//  phase 2 (last finishing block): reduce 2048 partials, add the 3 cos^2
//      terms computed from L2-hot standar_score, write scalar, reset counter.
__global__ __launch_bounds__(NTHR) void fused_loss_kernel(
    const float* __restrict__ x,
    const int* __restrict__ pol,      // int32 (JAX x64 disabled downcasts int64)
    const float* __restrict__ s,
    float* __restrict__ out)
{
    const float4* __restrict__ x4 = (const float4*)x;
    const float4* __restrict__ s4 = (const float4*)s;
    const int tid = threadIdx.x;

    // ---- phase 1: streaming squared-distance partial ----
    float a0 = 0.f, a1 = 0.f, a2 = 0.f, a3 = 0.f;
    int i = blockIdx.x * NTHR + tid;
#pragma unroll 4
    for (int k = 0; k < PER_THR; k++, i += NBLK * NTHR) {
        int row = i >> 9;         // i / D4
        int c   = i & (D4 - 1);   // i % D4
        int p = __ldg(&pol[row]);
        p = min(max(p, 0), 2);    // keep gather in-bounds
        float4 xv = x4[i];
        float4 sv = __ldg(&s4[p * D4 + c]);
        float d0 = xv.x - sv.x;
        float d1 = xv.y - sv.y;
        float d2 = xv.z - sv.z;
        float d3 = xv.w - sv.w;
        a0 += d0 * d0;  a1 += d1 * d1;
        a2 += d2 * d2;  a3 += d3 * d3;
    }
    float acc = (a0 + a1) + (a2 + a3);

    __shared__ float sm[NTHR];
    sm[tid] = acc;
    __syncthreads();
#pragma unroll
    for (int st = NTHR / 2; st > 0; st >>= 1) {
        if (tid < st) sm[tid] += sm[tid + st];
        __syncthreads();
    }

    __shared__ unsigned int s_islast;
    if (tid == 0) {
        g_partials[blockIdx.x] = sm[0];
        __threadfence();                       // make partial visible chip-wide
        unsigned int prev = atomicAdd(&g_count, 1u);
        s_islast = (prev == NBLK - 1) ? 1u : 0u;
    }
    __syncthreads();
    if (!s_islast) return;

    // ---- phase 2: last block folds everything ----
    float racc = 0.0f;
#pragma unroll
    for (int j = tid; j < NBLK; j += NTHR) racc += g_partials[j];

    // cos_(a,b) = dot(a,b) / sqrt(||a||^2) * sqrt(||b||^2)  (reference precedence)
    // => cos_^2 = dot^2 * ||b||^2 / ||a||^2
    float n0 = 0.f, n1 = 0.f, n2 = 0.f, d01 = 0.f, d02 = 0.f, d12 = 0.f;
    for (int j = tid; j < D_DIM; j += NTHR) {
        float a = s[j];
        float b = s[D_DIM + j];
        float c = s[2 * D_DIM + j];
        n0  += a * a;  n1  += b * b;  n2  += c * c;
        d01 += a * b;  d02 += a * c;  d12 += b * c;
    }

    __shared__ float rm[7][NTHR];
    rm[0][tid] = racc;
    rm[1][tid] = n0;  rm[2][tid] = n1;  rm[3][tid] = n2;
    rm[4][tid] = d01; rm[5][tid] = d02; rm[6][tid] = d12;
    __syncthreads();
#pragma unroll
    for (int st = NTHR / 2; st > 0; st >>= 1) {
        if (tid < st) {
#pragma unroll
            for (int k = 0; k < 7; k++) rm[k][tid] += rm[k][tid + st];
        }
        __syncthreads();
    }

    if (tid == 0) {
        float L   = rm[0][0];
        float N0  = rm[1][0], N1 = rm[2][0], N2 = rm[3][0];
        float D01 = rm[4][0], D02 = rm[5][0], D12 = rm[6][0];
        float c01 = D01 * D01 * (N1 / N0);
        float c02 = D02 * D02 * (N2 / N0);
        float c12 = D12 * D12 * (N2 / N1);
        out[0] = L + c01 + c02 + c12;
        g_count = 0;                 // reset for next graph replay
    }
}

extern "C" void kernel_launch(void* const* d_in, const int* in_sizes, int n_in,
                              void* d_out, int out_size)
{
    const float* x   = (const float*)d_in[0];   // inputs [16384, 2048] f32
    const int*   pol = (const int*)d_in[1];     // polarity [16384] int32
    const float* s   = (const float*)d_in[2];   // standar_score [3, 2048] f32
    float* out = (float*)d_out;

    fused_loss_kernel<<<NBLK, NTHR>>>(x, pol, s, out);
}

// round 5
// speedup vs baseline: 1.0656x; 1.0092x over previous
#include <cuda_runtime.h>

// Problem shape (fixed by the dataset)
#define B_ROWS   16384
#define D_DIM    2048
#define D4       (D_DIM / 4)          // 512 float4 per row
#define NBLK     2048
#define NTHR     256                   // 8 warps/block, 1 warp per row, 16384 rows exact
#define WARPS_PER_BLK (NTHR / 32)

__device__ float g_partials[NBLK];
__device__ unsigned int g_count;   // zero-init at load; reset by last block each run

// One warp per row. Lane owns 16 float4 slots (lane + 32k), processed as two
// batches of 8 with explicit prefetch arrays -> 8 independent LDG.128 in
// flight per warp (MLP=8). polarity loaded once per row, hoisted out of the
// stream loop. Last finishing block folds partials + the 3 cos^2 terms.
__global__ __launch_bounds__(NTHR) void fused_loss_kernel(
    const float* __restrict__ x,
    const int* __restrict__ pol,      // int32 (JAX x64-disabled downcasts int64)
    const float* __restrict__ s,
    float* __restrict__ out)
{
    const float4* __restrict__ x4 = (const float4*)x;
    const float4* __restrict__ s4 = (const float4*)s;
    const int tid  = threadIdx.x;
    const int wid  = tid >> 5;
    const int lane = tid & 31;

    const int row = blockIdx.x * WARPS_PER_BLK + wid;   // < 16384 always

    int p = __ldg(&pol[row]);
    p = min(max(p, 0), 2);                              // keep gather in-bounds

    const float4* __restrict__ xr = x4 + row * D4;
    const float4* __restrict__ sr = s4 + p * D4;

    float a0 = 0.f, a1 = 0.f, a2 = 0.f, a3 = 0.f;

#pragma unroll
    for (int half = 0; half < 2; half++) {
        const int base = half * 256 + lane;
        float4 xv[8];
#pragma unroll
        for (int k = 0; k < 8; k++)                     // 8 independent stream loads
            xv[k] = xr[base + 32 * k];
#pragma unroll
        for (int k = 0; k < 8; k++) {
            float4 sv = __ldg(&sr[base + 32 * k]);      // L1-hot 24KB
            float d0 = xv[k].x - sv.x;
            float d1 = xv[k].y - sv.y;
            float d2 = xv[k].z - sv.z;
            float d3 = xv[k].w - sv.w;
            a0 += d0 * d0;  a1 += d1 * d1;
            a2 += d2 * d2;  a3 += d3 * d3;
        }
    }
    float acc = (a0 + a1) + (a2 + a3);

    // warp reduce
#pragma unroll
    for (int off = 16; off > 0; off >>= 1)
        acc += __shfl_down_sync(0xFFFFFFFFu, acc, off);

    __shared__ float wsum[WARPS_PER_BLK];
    if (lane == 0) wsum[wid] = acc;
    __syncthreads();

    __shared__ unsigned int s_islast;
    if (tid == 0) {
        float bsum = 0.f;
#pragma unroll
        for (int w = 0; w < WARPS_PER_BLK; w++) bsum += wsum[w];
        g_partials[blockIdx.x] = bsum;
        __threadfence();
        unsigned int prev = atomicAdd(&g_count, 1u);
        s_islast = (prev == NBLK - 1) ? 1u : 0u;
    }
    __syncthreads();
    if (!s_islast) return;

    // ---- last block: fold partials + cos^2 terms ----
    float racc = 0.0f;
    for (int j = tid; j < NBLK; j += NTHR) racc += g_partials[j];

    // cos_(a,b) = dot(a,b) / sqrt(||a||^2) * sqrt(||b||^2) (reference precedence)
    // => cos_^2 = dot^2 * ||b||^2 / ||a||^2
    float n0 = 0.f, n1 = 0.f, n2 = 0.f, d01 = 0.f, d02 = 0.f, d12 = 0.f;
    for (int j = tid; j < D_DIM; j += NTHR) {
        float a = s[j];
        float b = s[D_DIM + j];
        float c = s[2 * D_DIM + j];
        n0  += a * a;  n1  += b * b;  n2  += c * c;
        d01 += a * b;  d02 += a * c;  d12 += b * c;
    }

    __shared__ float rm[7][NTHR];
    rm[0][tid] = racc;
    rm[1][tid] = n0;  rm[2][tid] = n1;  rm[3][tid] = n2;
    rm[4][tid] = d01; rm[5][tid] = d02; rm[6][tid] = d12;
    __syncthreads();
#pragma unroll
    for (int st = NTHR / 2; st > 0; st >>= 1) {
        if (tid < st) {
#pragma unroll
            for (int k = 0; k < 7; k++) rm[k][tid] += rm[k][tid + st];
        }
        __syncthreads();
    }

    if (tid == 0) {
        float L   = rm[0][0];
        float N0  = rm[1][0], N1 = rm[2][0], N2 = rm[3][0];
        float D01 = rm[4][0], D02 = rm[5][0], D12 = rm[6][0];
        float c01 = D01 * D01 * (N1 / N0);
        float c02 = D02 * D02 * (N2 / N0);
        float c12 = D12 * D12 * (N2 / N1);
        out[0] = L + c01 + c02 + c12;
        g_count = 0;                 // reset for next graph replay
    }
}

extern "C" void kernel_launch(void* const* d_in, const int* in_sizes, int n_in,
                              void* d_out, int out_size)
{
    const float* x   = (const float*)d_in[0];   // inputs [16384, 2048] f32
    const int*   pol = (const int*)d_in[1];     // polarity [16384] int32
    const float* s   = (const float*)d_in[2];   // standar_score [3, 2048] f32
    float* out = (float*)d_out;

    fused_loss_kernel<<<NBLK, NTHR>>>(x, pol, s, out);
}